// round 11
// baseline (speedup 1.0000x reference)
#include <cuda_runtime.h>

// ---------------------------------------------------------------------------
// R11: R9 structure (fused 2-layer LSTM, 4 elements/thread as 2 f16x2
//      element-pairs, HFMA2 MACs, f16x2 state) squeezed to 5 blocks/SM.
// R10 (NE=8) lost a block and regressed -> the 128-reg occupancy cliff
// dominates. This round trims live state to fit the NEXT cliff (<=102 regs,
// 5 blocks): per-sub-step float2 x-loads packed immediately (was float4
// staging across 2 sub-steps), packed f32x2 readout, Wout loaded per
// sub-step, __launch_bounds__(128, 5).
// ---------------------------------------------------------------------------

#define T_STEPS 50
typedef unsigned int u32;
typedef unsigned long long ull;

__device__ __forceinline__ float ex2f(float x) {
    float r; asm("ex2.approx.f32 %0, %1;" : "=f"(r) : "f"(x)); return r;
}
__device__ __forceinline__ float rcpf(float x) {
    float r; asm("rcp.approx.f32 %0, %1;" : "=f"(r) : "f"(x)); return r;
}
__device__ __forceinline__ ull pk2(float lo, float hi) {
    ull r; asm("mov.b64 %0, {%1, %2};" : "=l"(r) : "f"(lo), "f"(hi)); return r;
}
__device__ __forceinline__ void upk2(ull v, float& lo, float& hi) {
    asm("mov.b64 {%0, %1}, %2;" : "=f"(lo), "=f"(hi) : "l"(v));
}
__device__ __forceinline__ ull ffma2(ull a, ull b, ull c) {
    ull d; asm("fma.rn.f32x2 %0, %1, %2, %3;" : "=l"(d) : "l"(a), "l"(b), "l"(c));
    return d;
}

// ---- f16x2 helpers: lo half = even element, hi half = odd element ----------
__device__ __forceinline__ u32 h2pack(float lo, float hi) {
    u32 p; asm("cvt.rn.f16x2.f32 %0, %1, %2;" : "=r"(p) : "f"(hi), "f"(lo));
    return p;
}
__device__ __forceinline__ u32 h2dup(float w) {      // (w, w)
    u32 p; asm("cvt.rn.f16x2.f32 %0, %1, %1;" : "=r"(p) : "f"(w));
    return p;
}
__device__ __forceinline__ ull h2f32x2(u32 p) {      // f16x2 -> packed f32x2
    float lo, hi;
    asm("{\n\t.reg .b16 l, h;\n\tmov.b32 {l, h}, %2;\n\t"
        "cvt.f32.f16 %0, l;\n\tcvt.f32.f16 %1, h;\n\t}"
        : "=f"(lo), "=f"(hi) : "r"(p));
    return pk2(lo, hi);
}
__device__ __forceinline__ u32 hfma2(u32 a, u32 b, u32 c) {
    u32 d; asm("fma.rn.f16x2 %0, %1, %2, %3;" : "=r"(d) : "r"(a), "r"(b), "r"(c));
    return d;
}
__device__ __forceinline__ u32 hmul2(u32 a, u32 b) {
    u32 d; asm("mul.rn.f16x2 %0, %1, %2;" : "=r"(d) : "r"(a), "r"(b)); return d;
}
__device__ __forceinline__ u32 h2tanh(u32 p) {
    u32 r; asm("tanh.approx.f16x2 %0, %1;" : "=r"(r) : "r"(p)); return r;
}
// sigmoid of prescaled pre-act (x0.5 folded into weights): 0.5*tanh(y)+0.5
__device__ __forceinline__ u32 h2sig(u32 p) {
    u32 r;
    asm("{\n\ttanh.approx.f16x2 %0, %1;\n\t"
        "fma.rn.f16x2 %0, %0, %2, %2;\n\t}"
        : "=r"(r) : "r"(p), "r"(0x38003800u));
    return r;
}

// Pointwise LSTM block for one element-pair, all f16x2. c2 is f16x2 cell.
__device__ __forceinline__ u32 act_pair(u32 yi, u32 yf, u32 yg, u32 yo, u32& c2)
{
    u32 si = h2sig(yi);
    u32 sf = h2sig(yf);
    u32 so = h2sig(yo);
    u32 tg = h2tanh(yg);
    c2 = hfma2(sf, c2, hmul2(si, tg));
    return hmul2(so, h2tanh(c2));
}

#define NP 2            // element-pairs per thread
#define NE (2 * NP)     // elements per thread

__global__ __launch_bounds__(128, 5) void lstm_h2o5(
    const float* __restrict__ x,     // [B, T, 2]
    const float* __restrict__ Wih0,  // [16, 2]
    const float* __restrict__ Whh0,  // [16, 4]
    const float* __restrict__ bih0,
    const float* __restrict__ bhh0,
    const float* __restrict__ Wih1,  // [16, 4]
    const float* __restrict__ Whh1,  // [16, 4]
    const float* __restrict__ bih1,
    const float* __restrict__ bhh1,
    const float* __restrict__ Wout,  // [1, 200], col = t*4 + u
    const float* __restrict__ bout,
    float* __restrict__ out,
    int B)
{
    int g = blockIdx.x * 128 + threadIdx.x;
    int q = g >> 2;            // quad owns elements NE*q .. NE*q+NE-1
    int u = g & 3;             // hidden unit owned by this lane
    int eA = NE * q;
    if (eA >= B) return;
    int base = (threadIdx.x & 31) & ~3;

    // Gate rows for unit u (PyTorch order): i=u, f=4+u, g=8+u, o=12+u.
    // Sigmoid gates (i,f,o) scaled by 0.5; g-gate by 1.
    const int   row[4] = { u, 4 + u, 8 + u, 12 + u };
    const float scl[4] = { 0.5f, 0.5f, 1.0f, 0.5f };

    // Duplicated f16x2 weights (shared across all 4 elements).
    u32 wi0h[4][2], wh0h[4][4], bh0[4];
    u32 wi1h[4][4], wh1h[4][4], bh1[4];
#pragma unroll
    for (int G = 0; G < 4; G++) {
        int r = row[G];
        float s = scl[G];
#pragma unroll
        for (int k = 0; k < 2; k++)
            wi0h[G][k] = h2dup(s * __ldg(&Wih0[r * 2 + k]));
#pragma unroll
        for (int k = 0; k < 4; k++) {
            wh0h[G][k] = h2dup(s * __ldg(&Whh0[r * 4 + k]));
            wi1h[G][k] = h2dup(s * __ldg(&Wih1[r * 4 + k]));
            wh1h[G][k] = h2dup(s * __ldg(&Whh1[r * 4 + k]));
        }
        bh0[G] = h2dup(s * (__ldg(&bih0[r]) + __ldg(&bhh0[r])));
        bh1[G] = h2dup(s * (__ldg(&bih1[r]) + __ldg(&bhh1[r])));
    }

    // State: f16x2 cell per pair per layer; f16x2 h broadcasts; f32x2 readout.
    u32 c20[NP], c21[NP];
    u32 hb0[NP][4], hb1[NP][4];
    ull z2[NP];
#pragma unroll
    for (int P = 0; P < NP; P++) {
        c20[P] = c21[P] = 0u;
        z2[P] = 0ull;
#pragma unroll
        for (int k = 0; k < 4; k++) { hb0[P][k] = 0u; hb1[P][k] = 0u; }
    }

    const float2* xb = reinterpret_cast<const float2*>(x + (size_t)eA * (T_STEPS * 2));

#pragma unroll 1
    for (int t = 0; t < T_STEPS; ++t) {
        u32 h20[NP], h21[NP];

        // x for this step: one float2 per element, packed immediately.
        u32 xq[NP][2];
#pragma unroll
        for (int P = 0; P < NP; P++) {
            float2 va = __ldg(&xb[t + (2 * P) * T_STEPS]);
            float2 vb = __ldg(&xb[t + (2 * P + 1) * T_STEPS]);
            xq[P][0] = h2pack(va.x, vb.x);
            xq[P][1] = h2pack(va.y, vb.y);
        }

        // ---- layer 0: x-terms first (ready early), h-terms after ----
#pragma unroll
        for (int P = 0; P < NP; P++) {
            u32 yi = hfma2(wi0h[0][0], xq[P][0], bh0[0]);
            u32 yf = hfma2(wi0h[1][0], xq[P][0], bh0[1]);
            u32 yg = hfma2(wi0h[2][0], xq[P][0], bh0[2]);
            u32 yo = hfma2(wi0h[3][0], xq[P][0], bh0[3]);
            yi = hfma2(wi0h[0][1], xq[P][1], yi);
            yf = hfma2(wi0h[1][1], xq[P][1], yf);
            yg = hfma2(wi0h[2][1], xq[P][1], yg);
            yo = hfma2(wi0h[3][1], xq[P][1], yo);
#pragma unroll
            for (int k = 0; k < 4; k++) {
                yi = hfma2(wh0h[0][k], hb0[P][k], yi);
                yf = hfma2(wh0h[1][k], hb0[P][k], yf);
                yg = hfma2(wh0h[2][k], hb0[P][k], yg);
                yo = hfma2(wh0h[3][k], hb0[P][k], yo);
            }
            h20[P] = act_pair(yi, yf, yg, yo, c20[P]);
        }
        // packed shfl broadcast of layer0 h
#pragma unroll
        for (int P = 0; P < NP; P++) {
#pragma unroll
            for (int k = 0; k < 4; k++)
                hb0[P][k] = __shfl_sync(0xFFFFFFFFu, h20[P], base + k);
        }

        // ---- layer 1: recurrent (old hb1) first, fresh hb0 last ----
#pragma unroll
        for (int P = 0; P < NP; P++) {
            u32 yi = hfma2(wh1h[0][0], hb1[P][0], bh1[0]);
            u32 yf = hfma2(wh1h[1][0], hb1[P][0], bh1[1]);
            u32 yg = hfma2(wh1h[2][0], hb1[P][0], bh1[2]);
            u32 yo = hfma2(wh1h[3][0], hb1[P][0], bh1[3]);
#pragma unroll
            for (int k = 1; k < 4; k++) {
                yi = hfma2(wh1h[0][k], hb1[P][k], yi);
                yf = hfma2(wh1h[1][k], hb1[P][k], yf);
                yg = hfma2(wh1h[2][k], hb1[P][k], yg);
                yo = hfma2(wh1h[3][k], hb1[P][k], yo);
            }
#pragma unroll
            for (int k = 0; k < 4; k++) {
                yi = hfma2(wi1h[0][k], hb0[P][k], yi);
                yf = hfma2(wi1h[1][k], hb0[P][k], yf);
                yg = hfma2(wi1h[2][k], hb0[P][k], yg);
                yo = hfma2(wi1h[3][k], hb0[P][k], yo);
            }
            h21[P] = act_pair(yi, yf, yg, yo, c21[P]);
        }

        // readout (packed f32x2) + packed shfl broadcast of layer1 h
        {
            float wcur = __ldg(&Wout[t * 4 + u]);
            ull wde = pk2(wcur, wcur);
#pragma unroll
            for (int P = 0; P < NP; P++) {
                z2[P] = ffma2(h2f32x2(h21[P]), wde, z2[P]);
#pragma unroll
                for (int k = 0; k < 4; k++)
                    hb1[P][k] = __shfl_sync(0xFFFFFFFFu, h21[P], base + k);
            }
        }
    }

    // quad reduction of readouts; lane u==0 stores a coalesced float4
    float z[NE];
#pragma unroll
    for (int P = 0; P < NP; P++) upk2(z2[P], z[2 * P], z[2 * P + 1]);
#pragma unroll
    for (int e = 0; e < NE; e++) {
        z[e] += __shfl_xor_sync(0xFFFFFFFFu, z[e], 1);
        z[e] += __shfl_xor_sync(0xFFFFFFFFu, z[e], 2);
    }
    if (u == 0) {
        float bo = __ldg(&bout[0]);
        float4 r;
        r.x = rcpf(1.0f + ex2f(-1.442695040888963f * (z[0] + bo)));
        r.y = rcpf(1.0f + ex2f(-1.442695040888963f * (z[1] + bo)));
        r.z = rcpf(1.0f + ex2f(-1.442695040888963f * (z[2] + bo)));
        r.w = rcpf(1.0f + ex2f(-1.442695040888963f * (z[3] + bo)));
        *reinterpret_cast<float4*>(out + eA) = r;
    }
}

// ---------------------------------------------------------------------------
extern "C" void kernel_launch(void* const* d_in, const int* in_sizes, int n_in,
                              void* d_out, int out_size)
{
    const float* x    = (const float*)d_in[0];
    const float* Wih0 = (const float*)d_in[1];
    const float* Whh0 = (const float*)d_in[2];
    const float* bih0 = (const float*)d_in[3];
    const float* bhh0 = (const float*)d_in[4];
    const float* Wih1 = (const float*)d_in[5];
    const float* Whh1 = (const float*)d_in[6];
    const float* bih1 = (const float*)d_in[7];
    const float* bhh1 = (const float*)d_in[8];
    const float* Wout = (const float*)d_in[9];
    const float* bout = (const float*)d_in[10];

    int B = in_sizes[0] / (T_STEPS * 2);
    int threads = B;                   // 4 lanes per 4 elements
    int grid = (threads + 127) / 128;

    lstm_h2o5<<<grid, 128>>>(x, Wih0, Whh0, bih0, bhh0,
                             Wih1, Whh1, bih1, bhh1,
                             Wout, bout, (float*)d_out, B);
}

// round 12
// speedup vs baseline: 1.1735x; 1.1735x over previous
#include <cuda_runtime.h>

// ---------------------------------------------------------------------------
// R12: Cross-layer software-pipelined fused 2-layer LSTM (H=4, I=2, T=50)
//      + readout; 4 elements/thread as 2 f16x2 element-pairs (R9 datapath:
//      HFMA2 MACs, f16x2 activations/cell, f32x2 readout).
// Phase t computes layer0[t] AND layer1[t-1] concurrently — both read only
// the PREVIOUS phase's broadcasts (hb0 = h0[t-1], hb1 = h1[t-2]) — then one
// merged shfl exchange publishes (h0[t], h1[t-1]). This halves the number of
// shfl barriers per step and doubles the independent FMA burst between them
// (R9: layer1 waited on layer0's broadcast inside the same step; fma=62%).
// x staging: float4 per 2 steps (R11's per-step float2 doubled sector
// traffic and regressed). Head peel: layer0[0]; tail drain: layer1[49].
// ---------------------------------------------------------------------------

#define T_STEPS 50
typedef unsigned int u32;
typedef unsigned long long ull;

__device__ __forceinline__ float ex2f(float x) {
    float r; asm("ex2.approx.f32 %0, %1;" : "=f"(r) : "f"(x)); return r;
}
__device__ __forceinline__ float rcpf(float x) {
    float r; asm("rcp.approx.f32 %0, %1;" : "=f"(r) : "f"(x)); return r;
}
__device__ __forceinline__ ull pk2(float lo, float hi) {
    ull r; asm("mov.b64 %0, {%1, %2};" : "=l"(r) : "f"(lo), "f"(hi)); return r;
}
__device__ __forceinline__ void upk2(ull v, float& lo, float& hi) {
    asm("mov.b64 {%0, %1}, %2;" : "=f"(lo), "=f"(hi) : "l"(v));
}
__device__ __forceinline__ ull ffma2(ull a, ull b, ull c) {
    ull d; asm("fma.rn.f32x2 %0, %1, %2, %3;" : "=l"(d) : "l"(a), "l"(b), "l"(c));
    return d;
}

// ---- f16x2 helpers: lo half = even element, hi half = odd element ----------
__device__ __forceinline__ u32 h2pack(float lo, float hi) {
    u32 p; asm("cvt.rn.f16x2.f32 %0, %1, %2;" : "=r"(p) : "f"(hi), "f"(lo));
    return p;
}
__device__ __forceinline__ u32 h2dup(float w) {      // (w, w)
    u32 p; asm("cvt.rn.f16x2.f32 %0, %1, %1;" : "=r"(p) : "f"(w));
    return p;
}
__device__ __forceinline__ ull h2f32x2(u32 p) {      // f16x2 -> packed f32x2
    float lo, hi;
    asm("{\n\t.reg .b16 l, h;\n\tmov.b32 {l, h}, %2;\n\t"
        "cvt.f32.f16 %0, l;\n\tcvt.f32.f16 %1, h;\n\t}"
        : "=f"(lo), "=f"(hi) : "r"(p));
    return pk2(lo, hi);
}
__device__ __forceinline__ u32 hfma2(u32 a, u32 b, u32 c) {
    u32 d; asm("fma.rn.f16x2 %0, %1, %2, %3;" : "=r"(d) : "r"(a), "r"(b), "r"(c));
    return d;
}
__device__ __forceinline__ u32 hmul2(u32 a, u32 b) {
    u32 d; asm("mul.rn.f16x2 %0, %1, %2;" : "=r"(d) : "r"(a), "r"(b)); return d;
}
__device__ __forceinline__ u32 h2tanh(u32 p) {
    u32 r; asm("tanh.approx.f16x2 %0, %1;" : "=r"(r) : "r"(p)); return r;
}
// sigmoid of prescaled pre-act (x0.5 folded into weights): 0.5*tanh(y)+0.5
__device__ __forceinline__ u32 h2sig(u32 p) {
    u32 r;
    asm("{\n\ttanh.approx.f16x2 %0, %1;\n\t"
        "fma.rn.f16x2 %0, %0, %2, %2;\n\t}"
        : "=r"(r) : "r"(p), "r"(0x38003800u));
    return r;
}

// Pointwise LSTM block for one element-pair, all f16x2. c2 is f16x2 cell.
__device__ __forceinline__ u32 act_pair(u32 yi, u32 yf, u32 yg, u32 yo, u32& c2)
{
    u32 si = h2sig(yi);
    u32 sf = h2sig(yf);
    u32 so = h2sig(yo);
    u32 tg = h2tanh(yg);
    c2 = hfma2(sf, c2, hmul2(si, tg));
    return hmul2(so, h2tanh(c2));
}

// Layer-0 gates for one pair: x-terms first, h-terms after.
__device__ __forceinline__ u32 gates0(
    const u32 (&wi)[4][2], const u32 (&wh)[4][4], const u32 (&bb)[4],
    u32 x0, u32 x1, const u32 (&hb)[4], u32& c2)
{
    u32 yi = hfma2(wi[0][0], x0, bb[0]);
    u32 yf = hfma2(wi[1][0], x0, bb[1]);
    u32 yg = hfma2(wi[2][0], x0, bb[2]);
    u32 yo = hfma2(wi[3][0], x0, bb[3]);
    yi = hfma2(wi[0][1], x1, yi);
    yf = hfma2(wi[1][1], x1, yf);
    yg = hfma2(wi[2][1], x1, yg);
    yo = hfma2(wi[3][1], x1, yo);
#pragma unroll
    for (int k = 0; k < 4; k++) {
        yi = hfma2(wh[0][k], hb[k], yi);
        yf = hfma2(wh[1][k], hb[k], yf);
        yg = hfma2(wh[2][k], hb[k], yg);
        yo = hfma2(wh[3][k], hb[k], yo);
    }
    return act_pair(yi, yf, yg, yo, c2);
}

// Layer-1 gates for one pair: recurrent (hrec) first, input (hin) last.
__device__ __forceinline__ u32 gates1(
    const u32 (&wi)[4][4], const u32 (&wh)[4][4], const u32 (&bb)[4],
    const u32 (&hin)[4], const u32 (&hrec)[4], u32& c2)
{
    u32 yi = hfma2(wh[0][0], hrec[0], bb[0]);
    u32 yf = hfma2(wh[1][0], hrec[0], bb[1]);
    u32 yg = hfma2(wh[2][0], hrec[0], bb[2]);
    u32 yo = hfma2(wh[3][0], hrec[0], bb[3]);
#pragma unroll
    for (int k = 1; k < 4; k++) {
        yi = hfma2(wh[0][k], hrec[k], yi);
        yf = hfma2(wh[1][k], hrec[k], yf);
        yg = hfma2(wh[2][k], hrec[k], yg);
        yo = hfma2(wh[3][k], hrec[k], yo);
    }
#pragma unroll
    for (int k = 0; k < 4; k++) {
        yi = hfma2(wi[0][k], hin[k], yi);
        yf = hfma2(wi[1][k], hin[k], yf);
        yg = hfma2(wi[2][k], hin[k], yg);
        yo = hfma2(wi[3][k], hin[k], yo);
    }
    return act_pair(yi, yf, yg, yo, c2);
}

#define NP 2            // element-pairs per thread
#define NE (2 * NP)     // elements per thread

__global__ __launch_bounds__(128, 4) void lstm_pipe(
    const float* __restrict__ x,     // [B, T, 2]
    const float* __restrict__ Wih0,  // [16, 2]
    const float* __restrict__ Whh0,  // [16, 4]
    const float* __restrict__ bih0,
    const float* __restrict__ bhh0,
    const float* __restrict__ Wih1,  // [16, 4]
    const float* __restrict__ Whh1,  // [16, 4]
    const float* __restrict__ bih1,
    const float* __restrict__ bhh1,
    const float* __restrict__ Wout,  // [1, 200], col = t*4 + u
    const float* __restrict__ bout,
    float* __restrict__ out,
    int B)
{
    int g = blockIdx.x * 128 + threadIdx.x;
    int q = g >> 2;            // quad owns elements NE*q .. NE*q+NE-1
    int u = g & 3;             // hidden unit owned by this lane
    int eA = NE * q;
    if (eA >= B) return;
    int base = (threadIdx.x & 31) & ~3;

    // Gate rows for unit u (PyTorch order): i=u, f=4+u, g=8+u, o=12+u.
    const int   row[4] = { u, 4 + u, 8 + u, 12 + u };
    const float scl[4] = { 0.5f, 0.5f, 1.0f, 0.5f };

    u32 wi0h[4][2], wh0h[4][4], bh0[4];
    u32 wi1h[4][4], wh1h[4][4], bh1[4];
#pragma unroll
    for (int G = 0; G < 4; G++) {
        int r = row[G];
        float s = scl[G];
#pragma unroll
        for (int k = 0; k < 2; k++)
            wi0h[G][k] = h2dup(s * __ldg(&Wih0[r * 2 + k]));
#pragma unroll
        for (int k = 0; k < 4; k++) {
            wh0h[G][k] = h2dup(s * __ldg(&Whh0[r * 4 + k]));
            wi1h[G][k] = h2dup(s * __ldg(&Wih1[r * 4 + k]));
            wh1h[G][k] = h2dup(s * __ldg(&Whh1[r * 4 + k]));
        }
        bh0[G] = h2dup(s * (__ldg(&bih0[r]) + __ldg(&bhh0[r])));
        bh1[G] = h2dup(s * (__ldg(&bih1[r]) + __ldg(&bhh1[r])));
    }

    // State: hb0 = h0[t-1] broadcast; hb1 = h1[t-2] broadcast.
    u32 c20[NP], c21[NP];
    u32 hb0[NP][4], hb1[NP][4];
    ull z2[NP];
#pragma unroll
    for (int P = 0; P < NP; P++) {
        c20[P] = c21[P] = 0u;
        z2[P] = 0ull;
#pragma unroll
        for (int k = 0; k < 4; k++) { hb0[P][k] = 0u; hb1[P][k] = 0u; }
    }

    const float4* xb = reinterpret_cast<const float4*>(x + (size_t)eA * (T_STEPS * 2));

    // x staging: float4 covers 2 steps per element. xp[P][s][comp].
    u32 xp[NP][2][2];
#pragma unroll
    for (int P = 0; P < NP; P++) {
        float4 va = __ldg(&xb[0 + (2 * P) * (T_STEPS / 2)]);
        float4 vb = __ldg(&xb[0 + (2 * P + 1) * (T_STEPS / 2)]);
        xp[P][0][0] = h2pack(va.x, vb.x);
        xp[P][0][1] = h2pack(va.y, vb.y);
        xp[P][1][0] = h2pack(va.z, vb.z);
        xp[P][1][1] = h2pack(va.w, vb.w);
    }

    u32 h20[NP], h21[NP];

    // ---- HEAD phase t=0: layer0 only, publish hb0 = h0[0] ----
#pragma unroll
    for (int P = 0; P < NP; P++)
        h20[P] = gates0(wi0h, wh0h, bh0, xp[P][0][0], xp[P][0][1], hb0[P], c20[P]);
#pragma unroll
    for (int P = 0; P < NP; P++)
#pragma unroll
        for (int k = 0; k < 4; k++)
            hb0[P][k] = __shfl_sync(0xFFFFFFFFu, h20[P], base + k);

    // ---- HEAD phase t=1: layer0[1] || layer1[0]; publish both ----
    {
#pragma unroll
        for (int P = 0; P < NP; P++)
            h20[P] = gates0(wi0h, wh0h, bh0, xp[P][1][0], xp[P][1][1], hb0[P], c20[P]);
#pragma unroll
        for (int P = 0; P < NP; P++)
            h21[P] = gates1(wi1h, wh1h, bh1, hb0[P], hb1[P], c21[P]);
        float wv = __ldg(&Wout[0 * 4 + u]);
        ull wde = pk2(wv, wv);
#pragma unroll
        for (int P = 0; P < NP; P++) z2[P] = ffma2(h2f32x2(h21[P]), wde, z2[P]);
#pragma unroll
        for (int P = 0; P < NP; P++) {
#pragma unroll
            for (int k = 0; k < 4; k++) {
                hb0[P][k] = __shfl_sync(0xFFFFFFFFu, h20[P], base + k);
                hb1[P][k] = __shfl_sync(0xFFFFFFFFu, h21[P], base + k);
            }
        }
    }

    // ---- MAIN: tt = 1..24; phases t0=2tt (layer1: t0-1), t1=2tt+1 (layer1: t0)
#pragma unroll 1
    for (int tt = 1; tt < T_STEPS / 2; ++tt) {
#pragma unroll
        for (int P = 0; P < NP; P++) {
            float4 va = __ldg(&xb[tt + (2 * P) * (T_STEPS / 2)]);
            float4 vb = __ldg(&xb[tt + (2 * P + 1) * (T_STEPS / 2)]);
            xp[P][0][0] = h2pack(va.x, vb.x);
            xp[P][0][1] = h2pack(va.y, vb.y);
            xp[P][1][0] = h2pack(va.z, vb.z);
            xp[P][1][1] = h2pack(va.w, vb.w);
        }
        float woA = __ldg(&Wout[(2 * tt - 1) * 4 + u]);
        float woB = __ldg(&Wout[(2 * tt) * 4 + u]);

#pragma unroll
        for (int s = 0; s < 2; s++) {
            // layer0[t] and layer1[t-1]: both depend only on prior broadcasts
#pragma unroll
            for (int P = 0; P < NP; P++)
                h20[P] = gates0(wi0h, wh0h, bh0, xp[P][s][0], xp[P][s][1],
                                hb0[P], c20[P]);
#pragma unroll
            for (int P = 0; P < NP; P++)
                h21[P] = gates1(wi1h, wh1h, bh1, hb0[P], hb1[P], c21[P]);

            float wv = s ? woB : woA;
            ull wde = pk2(wv, wv);
#pragma unroll
            for (int P = 0; P < NP; P++)
                z2[P] = ffma2(h2f32x2(h21[P]), wde, z2[P]);

            // merged exchange: publish h0[t] and h1[t-1] together
#pragma unroll
            for (int P = 0; P < NP; P++) {
#pragma unroll
                for (int k = 0; k < 4; k++) {
                    hb0[P][k] = __shfl_sync(0xFFFFFFFFu, h20[P], base + k);
                    hb1[P][k] = __shfl_sync(0xFFFFFFFFu, h21[P], base + k);
                }
            }
        }
    }

    // ---- TAIL: layer1[49] (hb0 = h0[49], hb1 = h1[48]); no broadcast ----
    {
#pragma unroll
        for (int P = 0; P < NP; P++)
            h21[P] = gates1(wi1h, wh1h, bh1, hb0[P], hb1[P], c21[P]);
        float wv = __ldg(&Wout[(T_STEPS - 1) * 4 + u]);
        ull wde = pk2(wv, wv);
#pragma unroll
        for (int P = 0; P < NP; P++) z2[P] = ffma2(h2f32x2(h21[P]), wde, z2[P]);
    }

    // quad reduction of readouts; lane u==0 stores a coalesced float4
    float z[NE];
#pragma unroll
    for (int P = 0; P < NP; P++) upk2(z2[P], z[2 * P], z[2 * P + 1]);
#pragma unroll
    for (int e = 0; e < NE; e++) {
        z[e] += __shfl_xor_sync(0xFFFFFFFFu, z[e], 1);
        z[e] += __shfl_xor_sync(0xFFFFFFFFu, z[e], 2);
    }
    if (u == 0) {
        float bo = __ldg(&bout[0]);
        float4 r;
        r.x = rcpf(1.0f + ex2f(-1.442695040888963f * (z[0] + bo)));
        r.y = rcpf(1.0f + ex2f(-1.442695040888963f * (z[1] + bo)));
        r.z = rcpf(1.0f + ex2f(-1.442695040888963f * (z[2] + bo)));
        r.w = rcpf(1.0f + ex2f(-1.442695040888963f * (z[3] + bo)));
        *reinterpret_cast<float4*>(out + eA) = r;
    }
}

// ---------------------------------------------------------------------------
extern "C" void kernel_launch(void* const* d_in, const int* in_sizes, int n_in,
                              void* d_out, int out_size)
{
    const float* x    = (const float*)d_in[0];
    const float* Wih0 = (const float*)d_in[1];
    const float* Whh0 = (const float*)d_in[2];
    const float* bih0 = (const float*)d_in[3];
    const float* bhh0 = (const float*)d_in[4];
    const float* Wih1 = (const float*)d_in[5];
    const float* Whh1 = (const float*)d_in[6];
    const float* bih1 = (const float*)d_in[7];
    const float* bhh1 = (const float*)d_in[8];
    const float* Wout = (const float*)d_in[9];
    const float* bout = (const float*)d_in[10];

    int B = in_sizes[0] / (T_STEPS * 2);
    int threads = B;                   // 4 lanes per 4 elements
    int grid = (threads + 127) / 128;

    lstm_pipe<<<grid, 128>>>(x, Wih0, Whh0, bih0, bhh0,
                             Wih1, Whh1, bih1, bhh1,
                             Wout, bout, (float*)d_out, B);
}